// round 5
// baseline (speedup 1.0000x reference)
#include <cuda_runtime.h>
#include <math.h>
#include <stdint.h>

// Problem constants
#define B_    256
#define T_    128
#define BT_   32768
#define NIN_  1024
#define H1_   512
#define E_    256
#define G3_   768      // 3*E
#define A_    16
#define CAT_  272      // E + A
#define SN_   1024     // step GEMM N = E (h_enc) + 3E (gh)
#define NB_CTAS 128    // phase-B grid (8 x 16)

// phase-B dynamic smem layout (floats)
#define BS_STRIDE 132
#define AS_STRIDE 17
#define OFF_AS    (CAT_ * BS_STRIDE)
#define OFF_YS    (OFF_AS + CAT_ * AS_STRIDE)
#define SMEM_B_FLOATS (OFF_YS + 16 * BS_STRIDE)
#define SMEM_B_BYTES  (SMEM_B_FLOATS * 4)

// tf32 GEMM smem layout (floats)
#define TF_PAD        136                   // 136 mod 32 == 8 -> conflict-free frags
#define TF_STAGE      (16 * TF_PAD)         // 2176 floats per array
#define TF_STAGE_TOT  (4 * TF_STAGE)        // As_hi | As_lo | Bs_hi | Bs_lo
#define TF_SMEM_FLOATS (2 * TF_STAGE_TOT)   // double-buffered
#define TF_SMEM_BYTES  (TF_SMEM_FLOATS * 4) // 69632 B

// ---------------- scratch (device globals; no allocation allowed) ----------------
__device__ float g_X1[BT_ * H1_];
__device__ float g_X2[BT_ * H1_];
__device__ float g_GI[BT_ * G3_];
__device__ float g_AENC[BT_ * A_];
__device__ float g_W34[H1_ * G3_];
__device__ float g_b34v[G3_];
__device__ float g_Wstep[CAT_ * SN_];      // [Whe | Whe@Whh]
__device__ float g_bstep[SN_];             // [bhe | bhe@Whh + bhh]
__device__ float g_Ha[B_ * E_];
__device__ float g_Hb[B_ * E_];
__device__ unsigned g_bar;

// ---------------- tf32 mma helper ------------------------------------------------
__device__ __forceinline__ void mma_tf32(float (&c)[4], const float (&a)[4],
                                         const float (&b)[2])
{
    asm volatile(
        "mma.sync.aligned.m16n8k8.row.col.f32.tf32.tf32.f32 "
        "{%0,%1,%2,%3}, {%4,%5,%6,%7}, {%8,%9}, {%0,%1,%2,%3};\n"
        : "+f"(c[0]), "+f"(c[1]), "+f"(c[2]), "+f"(c[3])
        : "r"(__float_as_uint(a[0])), "r"(__float_as_uint(a[1])),
          "r"(__float_as_uint(a[2])), "r"(__float_as_uint(a[3])),
          "r"(__float_as_uint(b[0])), "r"(__float_as_uint(b[1])));
}

__device__ __forceinline__ float tf32_hi(float v)
{
    return __uint_as_float(__float_as_uint(v) & 0xFFFFE000u);
}

// ---------------- tf32x3 GEMM: C[M,N] = A[M,K]@B[K,N] (+bias) --------------------
// 128x128 CTA tile, BK=16, 256 threads (8 warps, 4x2), warp tile 32x64.
// A row-major, B row-major. Requires K%16==0, N%128==0. M guarded.
// Accuracy: 3-pass tf32 (hi*hi + hi*lo + lo*hi) ~ fp32.
__global__ void __launch_bounds__(256) tf32gemm(
    const float* __restrict__ A, const float* __restrict__ Bm,
    const float* __restrict__ bias, float* __restrict__ C,
    int M, int N, int K, int lda, int ldb, int ldc)
{
    extern __shared__ float ts[];
    const int tid  = threadIdx.x;
    const int m0   = blockIdx.y * 128;
    const int n0   = blockIdx.x * 128;
    const int lane = tid & 31;
    const int warp = tid >> 5;
    const int gid  = lane >> 2;       // 0..7
    const int tig  = lane & 3;        // 0..3
    const int wm   = warp & 3;        // 32-row band
    const int wn   = warp >> 2;       // 64-col band

    float c[2][8][4];
#pragma unroll
    for (int i = 0; i < 2; i++)
#pragma unroll
        for (int j = 0; j < 8; j++)
#pragma unroll
            for (int e = 0; e < 4; e++) c[i][j][e] = 0.f;

    int stage = 0;
    for (int k0 = 0; k0 < K; k0 += 16, stage ^= 1) {
        float* As_h = ts + stage * TF_STAGE_TOT;
        float* As_l = As_h + TF_STAGE;
        float* Bs_h = As_l + TF_STAGE;
        float* Bs_l = Bs_h + TF_STAGE;

        // ---- load + split A tile: 128 rows x 16 k, k-major smem [k][row] ----
#pragma unroll
        for (int it = 0; it < 2; it++) {
            int idx = tid + it * 256;           // 0..511
            int row = idx >> 2;
            int kq  = (idx & 3) << 2;
            float4 av = make_float4(0.f, 0.f, 0.f, 0.f);
            if (m0 + row < M)
                av = *reinterpret_cast<const float4*>(&A[(size_t)(m0 + row) * lda + k0 + kq]);
            float vs[4] = {av.x, av.y, av.z, av.w};
#pragma unroll
            for (int j = 0; j < 4; j++) {
                float hi = tf32_hi(vs[j]);
                As_h[(kq + j) * TF_PAD + row] = hi;
                As_l[(kq + j) * TF_PAD + row] = vs[j] - hi;
            }
        }
        // ---- load + split B tile: 16 k x 128 n, smem [k][n] ----
#pragma unroll
        for (int it = 0; it < 2; it++) {
            int idx = tid + it * 256;
            int kk = idx >> 5;
            int nq = (idx & 31) << 2;
            float4 bv = *reinterpret_cast<const float4*>(&Bm[(size_t)(k0 + kk) * ldb + n0 + nq]);
            float4 hv, lv;
            hv.x = tf32_hi(bv.x); lv.x = bv.x - hv.x;
            hv.y = tf32_hi(bv.y); lv.y = bv.y - hv.y;
            hv.z = tf32_hi(bv.z); lv.z = bv.z - hv.z;
            hv.w = tf32_hi(bv.w); lv.w = bv.w - hv.w;
            *reinterpret_cast<float4*>(&Bs_h[kk * TF_PAD + nq]) = hv;
            *reinterpret_cast<float4*>(&Bs_l[kk * TF_PAD + nq]) = lv;
        }
        __syncthreads();

        // ---- compute: 2 k8 sub-chunks ----
#pragma unroll
        for (int k8 = 0; k8 < 2; k8++) {
            const int kb = k8 * 8;
            float ah[2][4], al[2][4];
#pragma unroll
            for (int mt = 0; mt < 2; mt++) {
                int rb = wm * 32 + mt * 16;
                ah[mt][0] = As_h[(kb + tig) * TF_PAD + rb + gid];
                ah[mt][1] = As_h[(kb + tig) * TF_PAD + rb + gid + 8];
                ah[mt][2] = As_h[(kb + tig + 4) * TF_PAD + rb + gid];
                ah[mt][3] = As_h[(kb + tig + 4) * TF_PAD + rb + gid + 8];
                al[mt][0] = As_l[(kb + tig) * TF_PAD + rb + gid];
                al[mt][1] = As_l[(kb + tig) * TF_PAD + rb + gid + 8];
                al[mt][2] = As_l[(kb + tig + 4) * TF_PAD + rb + gid];
                al[mt][3] = As_l[(kb + tig + 4) * TF_PAD + rb + gid + 8];
            }
#pragma unroll
            for (int nt = 0; nt < 8; nt++) {
                int cb = wn * 64 + nt * 8;
                float bh[2], bl[2];
                bh[0] = Bs_h[(kb + tig) * TF_PAD + cb + gid];
                bh[1] = Bs_h[(kb + tig + 4) * TF_PAD + cb + gid];
                bl[0] = Bs_l[(kb + tig) * TF_PAD + cb + gid];
                bl[1] = Bs_l[(kb + tig + 4) * TF_PAD + cb + gid];
#pragma unroll
                for (int mt = 0; mt < 2; mt++) {
                    mma_tf32(c[mt][nt], ah[mt], bh);   // hi*hi
                    mma_tf32(c[mt][nt], ah[mt], bl);   // hi*lo
                    mma_tf32(c[mt][nt], al[mt], bh);   // lo*hi
                }
            }
        }
        __syncthreads();
    }

    // ---- epilogue: bias + store (float2 per fragment row) ----
#pragma unroll
    for (int mt = 0; mt < 2; mt++) {
#pragma unroll
        for (int nt = 0; nt < 8; nt++) {
            int col = n0 + wn * 64 + nt * 8 + tig * 2;
            float bx = 0.f, by = 0.f;
            if (bias) { bx = bias[col]; by = bias[col + 1]; }
            int row0 = m0 + wm * 32 + mt * 16 + gid;
            if (row0 < M) {
                float2 v = make_float2(c[mt][nt][0] + bx, c[mt][nt][1] + by);
                *reinterpret_cast<float2*>(&C[(size_t)row0 * ldc + col]) = v;
            }
            int row1 = row0 + 8;
            if (row1 < M) {
                float2 v = make_float2(c[mt][nt][2] + bx, c[mt][nt][3] + by);
                *reinterpret_cast<float2*>(&C[(size_t)row1 * ldc + col]) = v;
            }
        }
    }
}

// ---------------- fp32 GEMM (prep-only; exact path for fused weights) ------------
// 128x128 tile, BK=8, 256 threads, 8x8 micro-tile. K%8==0, N%128==0, M guarded.
__global__ void __launch_bounds__(256) sgemm128(
    const float* __restrict__ A, const float* __restrict__ Bm,
    const float* __restrict__ bias, float* __restrict__ C,
    int M, int N, int K, int lda, int ldb, int ldc)
{
    __shared__ float As[2][8][128];
    __shared__ float Bs[2][8][128];

    const int tid = threadIdx.x;
    const int m0 = blockIdx.y * 128;
    const int n0 = blockIdx.x * 128;

    const int ar = tid >> 1;
    const int ak = (tid & 1) * 4;
    const int br = tid >> 5;
    const int bn = (tid & 31) * 4;
    const int tx = tid & 15;
    const int ty = tid >> 4;

    float acc[8][8];
#pragma unroll
    for (int i = 0; i < 8; i++)
#pragma unroll
        for (int j = 0; j < 8; j++) acc[i][j] = 0.f;

    float4 av = make_float4(0.f, 0.f, 0.f, 0.f);
    if (m0 + ar < M)
        av = *reinterpret_cast<const float4*>(&A[(size_t)(m0 + ar) * lda + ak]);
    float4 bv = *reinterpret_cast<const float4*>(&Bm[(size_t)br * ldb + n0 + bn]);
    As[0][ak + 0][ar] = av.x;
    As[0][ak + 1][ar] = av.y;
    As[0][ak + 2][ar] = av.z;
    As[0][ak + 3][ar] = av.w;
    *reinterpret_cast<float4*>(&Bs[0][br][bn]) = bv;
    __syncthreads();

    int buf = 0;
    for (int k0 = 0; k0 < K; k0 += 8) {
        const bool more = (k0 + 8) < K;
        float4 av2, bv2;
        if (more) {
            av2 = make_float4(0.f, 0.f, 0.f, 0.f);
            if (m0 + ar < M)
                av2 = *reinterpret_cast<const float4*>(&A[(size_t)(m0 + ar) * lda + k0 + 8 + ak]);
            bv2 = *reinterpret_cast<const float4*>(&Bm[(size_t)(k0 + 8 + br) * ldb + n0 + bn]);
        }
#pragma unroll
        for (int kk = 0; kk < 8; kk++) {
            float4 a0 = *reinterpret_cast<const float4*>(&As[buf][kk][ty * 4]);
            float4 a1 = *reinterpret_cast<const float4*>(&As[buf][kk][64 + ty * 4]);
            float4 b0 = *reinterpret_cast<const float4*>(&Bs[buf][kk][tx * 4]);
            float4 b1 = *reinterpret_cast<const float4*>(&Bs[buf][kk][64 + tx * 4]);
            float a[8] = {a0.x, a0.y, a0.z, a0.w, a1.x, a1.y, a1.z, a1.w};
            float b[8] = {b0.x, b0.y, b0.z, b0.w, b1.x, b1.y, b1.z, b1.w};
#pragma unroll
            for (int i = 0; i < 8; i++)
#pragma unroll
                for (int j = 0; j < 8; j++) acc[i][j] += a[i] * b[j];
        }
        if (more) {
            buf ^= 1;
            As[buf][ak + 0][ar] = av2.x;
            As[buf][ak + 1][ar] = av2.y;
            As[buf][ak + 2][ar] = av2.z;
            As[buf][ak + 3][ar] = av2.w;
            *reinterpret_cast<float4*>(&Bs[buf][br][bn]) = bv2;
            __syncthreads();
        }
    }

#pragma unroll
    for (int i = 0; i < 8; i++) {
        int m = m0 + ((i < 4) ? (ty * 4 + i) : (64 + ty * 4 + i - 4));
        if (m >= M) continue;
#pragma unroll
        for (int jh = 0; jh < 2; jh++) {
            int n = n0 + jh * 64 + tx * 4;
            float4 v;
            v.x = acc[i][jh * 4 + 0];
            v.y = acc[i][jh * 4 + 1];
            v.z = acc[i][jh * 4 + 2];
            v.w = acc[i][jh * 4 + 3];
            if (bias) {
                v.x += bias[n + 0]; v.y += bias[n + 1];
                v.z += bias[n + 2]; v.w += bias[n + 3];
            }
            *reinterpret_cast<float4*>(&C[(size_t)m * ldc + n]) = v;
        }
    }
}

// ---------------- BatchNorm (train, biased var) + ELU, in place ------------------
__global__ void bn_elu_kernel(float* __restrict__ X,
                              const float* __restrict__ gamma,
                              const float* __restrict__ beta)
{
    const int t = blockIdx.x;
    const int j = blockIdx.y * 128 + threadIdx.x;
    float s = 0.f, ss = 0.f;
    for (int b = 0; b < B_; b++) {
        float v = X[(size_t)(b * T_ + t) * H1_ + j];
        s += v; ss += v * v;
    }
    float mu  = s * (1.f / B_);
    float var = ss * (1.f / B_) - mu * mu;
    float sc  = gamma[j] * rsqrtf(var + 1e-5f);
    float sh  = beta[j] - mu * sc;
    for (int b = 0; b < B_; b++) {
        size_t idx = (size_t)(b * T_ + t) * H1_ + j;
        float y = X[idx] * sc + sh;
        X[idx] = (y > 0.f) ? y : expm1f(y);   // ELU alpha=1
    }
}

// ---------------- action encoder: AENC = actions @ Wae + bae --------------------
__global__ void aenc_kernel(const float* __restrict__ act,
                            const float* __restrict__ Wae,
                            const float* __restrict__ bae)
{
    int idx = blockIdx.x * blockDim.x + threadIdx.x;
    if (idx >= BT_ * A_) return;
    int r = idx >> 4, j = idx & 15;
    float acc = bae[j];
#pragma unroll
    for (int k = 0; k < 16; k++) acc += act[(r << 4) + k] * Wae[(k << 4) + j];
    g_AENC[idx] = acc;
}

// ---------------- weight-fusion prep ---------------------------------------------
__global__ void prep_bias_kernel(const float* __restrict__ b3,
                                 const float* __restrict__ bih,
                                 const float* __restrict__ Wih,
                                 const float* __restrict__ bhe,
                                 const float* __restrict__ bhh,
                                 const float* __restrict__ Whh)
{
    int j = blockIdx.x * blockDim.x + threadIdx.x;
    if (j < G3_) {
        float a1 = bih[j], a2 = bhh[j];
        for (int k = 0; k < E_; k++) {
            a1 += b3[k]  * Wih[k * G3_ + j];
            a2 += bhe[k] * Whh[k * G3_ + j];
        }
        g_b34v[j] = a1;
        g_bstep[E_ + j] = a2;
    }
    if (j < E_) g_bstep[j] = bhe[j];
}

__global__ void prep_whe_copy(const float* __restrict__ Whe)
{
    int idx = blockIdx.x * blockDim.x + threadIdx.x;
    if (idx >= CAT_ * E_) return;
    int i = idx / E_, j = idx - i * E_;
    g_Wstep[i * SN_ + j] = Whe[idx];
}

// zero h0 + reset grid barrier (runs every graph replay, before phase B)
__global__ void zero_kernel(float* p, int n)
{
    int i = blockIdx.x * blockDim.x + threadIdx.x;
    if (i == 0) g_bar = 0u;
    if (i < n) p[i] = 0.f;
}

// ---------------- phase B: persistent recurrence kernel --------------------------
// 128 CTAs (8 j-tiles x 16 b-tiles), 256 threads, 1 CTA/SM. Wstep slice resident
// in smem for all 128 steps. Hidden state read with __ldcg (L1 is stale across
// the software grid barrier; only L2 is coherent between SMs within one launch).
__global__ void __launch_bounds__(256) phaseB_kernel(
    float* __restrict__ Ha, float* __restrict__ Hb,
    const float* __restrict__ aenc, const float* __restrict__ GI,
    float* __restrict__ out)
{
    extern __shared__ float sm[];
    float* Bs = sm;                 // [CAT_][BS_STRIDE], 128 gathered cols
    float* As = sm + OFF_AS;        // [CAT_][AS_STRIDE], 16 batch rows
    float* Ys = sm + OFF_YS;        // [16][BS_STRIDE]

    const int tid = threadIdx.x;
    const int j0 = blockIdx.x * 32;
    const int b0 = blockIdx.y * 16;
    const int tx = tid & 31;
    const int ty = tid >> 5;

    for (int i = tid; i < CAT_ * 128; i += 256) {
        int k = i >> 7;
        int c = i & 127;
        int g = c >> 5;
        Bs[k * BS_STRIDE + c] = g_Wstep[k * SN_ + g * E_ + j0 + (c & 31)];
    }

    float bias_c[4];
#pragma unroll
    for (int q = 0; q < 4; q++) {
        int c = tx * 4 + q;
        int g = c >> 5;
        bias_c[q] = g_bstep[g * E_ + j0 + (c & 31)];
    }
    __syncthreads();

    float* hin = Ha;
    float* hout = Hb;

    for (int t = 0; t < T_; t++) {
        for (int i = tid; i < 16 * 256; i += 256) {
            int row = i >> 8, k = i & 255;
            As[k * AS_STRIDE + row] = __ldcg(&hin[(b0 + row) * E_ + k]);
        }
        {
            int row = tid >> 4, k2 = tid & 15;
            float v = 0.f;
            if (t > 0)
                v = aenc[((size_t)(b0 + row) * T_ + (t - 1)) * A_ + k2];
            As[(E_ + k2) * AS_STRIDE + row] = v;
        }
        __syncthreads();

        float acc0[4] = {0.f, 0.f, 0.f, 0.f};
        float acc1[4] = {0.f, 0.f, 0.f, 0.f};
#pragma unroll 4
        for (int k = 0; k < CAT_; k++) {
            float a0 = As[k * AS_STRIDE + ty];
            float a1 = As[k * AS_STRIDE + ty + 8];
            float4 b4 = *reinterpret_cast<const float4*>(&Bs[k * BS_STRIDE + tx * 4]);
            acc0[0] += a0 * b4.x; acc0[1] += a0 * b4.y;
            acc0[2] += a0 * b4.z; acc0[3] += a0 * b4.w;
            acc1[0] += a1 * b4.x; acc1[1] += a1 * b4.y;
            acc1[2] += a1 * b4.z; acc1[3] += a1 * b4.w;
        }

#pragma unroll
        for (int q = 0; q < 4; q++) {
            int c = tx * 4 + q;
            Ys[ty * BS_STRIDE + c]       = acc0[q] + bias_c[q];
            Ys[(ty + 8) * BS_STRIDE + c] = acc1[q] + bias_c[q];
        }
        __syncthreads();

        float* o = (t == T_ - 1) ? out : hout;
#pragma unroll
        for (int q = 0; q < 2; q++) {
            int oidx = tid * 2 + q;
            int rr = oidx >> 5;
            int jl = oidx & 31;
            int b = b0 + rr;
            int j = j0 + jl;
            float henc = Ys[rr * BS_STRIDE + jl];
            float ghr  = Ys[rr * BS_STRIDE + 32 + jl];
            float ghz  = Ys[rr * BS_STRIDE + 64 + jl];
            float ghn  = Ys[rr * BS_STRIDE + 96 + jl];
            size_t gb = ((size_t)b * T_ + t) * G3_ + j;
            float ir  = GI[gb];
            float iz  = GI[gb + E_];
            float inn = GI[gb + 2 * E_];
            float r = 1.f / (1.f + expf(-(ir + ghr)));
            float z = 1.f / (1.f + expf(-(iz + ghz)));
            float nn = tanhf(inn + r * ghn);
            o[b * E_ + j] = (1.f - z) * nn + z * henc;
        }

        __threadfence();
        __syncthreads();
        if (tid == 0) {
            atomicAdd(&g_bar, 1u);
            const unsigned target = (unsigned)NB_CTAS * (unsigned)(t + 1);
            while (*((volatile unsigned*)&g_bar) < target)
                __nanosleep(40);
            __threadfence();
        }
        __syncthreads();

        float* tmp = hin; hin = hout; hout = tmp;
    }
}

// ---------------- host orchestration ---------------------------------------------
extern "C" void kernel_launch(void* const* d_in, const int* in_sizes, int n_in,
                              void* d_out, int out_size)
{
    const float* obs = (const float*)d_in[0];
    const float* act = (const float*)d_in[1];
    const float* W1  = (const float*)d_in[2];
    const float* b1  = (const float*)d_in[3];
    const float* g1  = (const float*)d_in[4];
    const float* be1 = (const float*)d_in[5];
    const float* W2  = (const float*)d_in[6];
    const float* b2  = (const float*)d_in[7];
    const float* g2  = (const float*)d_in[8];
    const float* be2 = (const float*)d_in[9];
    const float* W3  = (const float*)d_in[10];
    const float* b3  = (const float*)d_in[11];
    const float* Wih = (const float*)d_in[12];
    const float* bih = (const float*)d_in[13];
    const float* Whh = (const float*)d_in[14];
    const float* bhh = (const float*)d_in[15];
    const float* Whe = (const float*)d_in[16];
    const float* bhe = (const float*)d_in[17];
    const float* Wae = (const float*)d_in[18];
    const float* bae = (const float*)d_in[19];
    float* out = (float*)d_out;

    float *X1p, *X2p, *GIp, *AEp, *W34p, *b34p, *Wstepp, *Hap, *Hbp;
    cudaGetSymbolAddress((void**)&X1p,   g_X1);
    cudaGetSymbolAddress((void**)&X2p,   g_X2);
    cudaGetSymbolAddress((void**)&GIp,   g_GI);
    cudaGetSymbolAddress((void**)&AEp,   g_AENC);
    cudaGetSymbolAddress((void**)&W34p,  g_W34);
    cudaGetSymbolAddress((void**)&b34p,  g_b34v);
    cudaGetSymbolAddress((void**)&Wstepp,g_Wstep);
    cudaGetSymbolAddress((void**)&Hap,   g_Ha);
    cudaGetSymbolAddress((void**)&Hbp,   g_Hb);

    // opt-in smem sizes (idempotent)
    cudaFuncSetAttribute(phaseB_kernel,
                         cudaFuncAttributeMaxDynamicSharedMemorySize, SMEM_B_BYTES);
    cudaFuncSetAttribute(tf32gemm,
                         cudaFuncAttributeMaxDynamicSharedMemorySize, TF_SMEM_BYTES);

    // ---- prep: fused weights (exact fp32), bias vectors, zero h0 + barrier ----
    prep_bias_kernel<<<3, 256>>>(b3, bih, Wih, bhe, bhh, Whh);
    prep_whe_copy<<<(CAT_ * E_ + 255) / 256, 256>>>(Whe);
    zero_kernel<<<(B_ * E_ + 255) / 256, 256>>>(Hap, B_ * E_);
    // W34 = W3 @ Wih   [512,768], K=256
    sgemm128<<<dim3(G3_ / 128, (H1_ + 127) / 128), 256>>>(
        W3, Wih, nullptr, W34p, H1_, G3_, E_, E_, G3_, G3_);
    // Wstep[:, 256:1024] = Whe @ Whh   [272,768], K=256 (ldc=1024, offset 256)
    sgemm128<<<dim3(G3_ / 128, (CAT_ + 127) / 128), 256>>>(
        Whe, Whh, nullptr, Wstepp + E_, CAT_, G3_, E_, E_, G3_, SN_);

    // ---- phase A: time-parallel precompute on tensor cores (tf32x3) ----
    tf32gemm<<<dim3(H1_ / 128, BT_ / 128), 256, TF_SMEM_BYTES>>>(
        obs, W1, b1, X1p, BT_, H1_, NIN_, NIN_, H1_, H1_);
    bn_elu_kernel<<<dim3(T_, H1_ / 128), 128>>>(X1p, g1, be1);
    tf32gemm<<<dim3(H1_ / 128, BT_ / 128), 256, TF_SMEM_BYTES>>>(
        X1p, W2, b2, X2p, BT_, H1_, H1_, H1_, H1_, H1_);
    bn_elu_kernel<<<dim3(T_, H1_ / 128), 128>>>(X2p, g2, be2);
    tf32gemm<<<dim3(G3_ / 128, BT_ / 128), 256, TF_SMEM_BYTES>>>(
        X2p, W34p, b34p, GIp, BT_, G3_, H1_, H1_, G3_, G3_);
    aenc_kernel<<<(BT_ * A_ + 255) / 256, 256>>>(act, Wae, bae);

    // ---- phase B: one persistent kernel, 128 steps, grid barrier per step ----
    phaseB_kernel<<<dim3(8, 16), 256, SMEM_B_BYTES>>>(Hap, Hbp, AEp, GIp, out);
}

// round 9
// speedup vs baseline: 1.0866x; 1.0866x over previous
#include <cuda_runtime.h>
#include <math.h>
#include <stdint.h>

// Problem constants
#define B_    256
#define T_    128
#define BT_   32768
#define NIN_  1024
#define H1_   512
#define E_    256
#define G3_   768      // 3*E
#define A_    16
#define CAT_  272      // E + A
#define SN_   1024     // step GEMM N = E (h_enc) + 3E (gh)
#define NB_CTAS 128    // phase-B grid (8 x 16)

// phase-B dynamic smem layout (floats)
#define BS_STRIDE 132
#define AS_STRIDE 17
#define OFF_AS    (CAT_ * BS_STRIDE)
#define OFF_YS    (OFF_AS + CAT_ * AS_STRIDE)
#define SMEM_B_FLOATS (OFF_YS + 16 * BS_STRIDE)
#define SMEM_B_BYTES  (SMEM_B_FLOATS * 4)

// tf32 GEMM smem layout (floats)
#define TF_PAD        136                   // 136 mod 32 == 8 -> conflict-free frags
#define TF_STAGE      (16 * TF_PAD)         // 2176 floats per array
#define TF_STAGE_TOT  (4 * TF_STAGE)        // As_hi | As_lo | Bs_hi | Bs_lo
#define TF_SMEM_FLOATS (2 * TF_STAGE_TOT)   // double-buffered
#define TF_SMEM_BYTES  (TF_SMEM_FLOATS * 4) // 69632 B

// ---------------- scratch (device globals; no allocation allowed) ----------------
__device__ float g_X1[BT_ * H1_];
__device__ float g_X2[BT_ * H1_];
__device__ float g_GI[BT_ * G3_];
__device__ float g_AENC[BT_ * A_];
__device__ float g_W34[H1_ * G3_];
__device__ float g_b34v[G3_];
__device__ float g_Wstep[CAT_ * SN_];      // [Whe | Whe@Whh]
__device__ float g_bstep[SN_];             // [bhe | bhe@Whh + bhh]
__device__ float g_Ha[B_ * E_];
__device__ float g_Hb[B_ * E_];
__device__ unsigned g_bar;

// ---------------- tf32 mma helper ------------------------------------------------
__device__ __forceinline__ void mma_tf32(float (&c)[4], const float (&a)[4],
                                         const float (&b)[2])
{
    asm volatile(
        "mma.sync.aligned.m16n8k8.row.col.f32.tf32.tf32.f32 "
        "{%0,%1,%2,%3}, {%4,%5,%6,%7}, {%8,%9}, {%0,%1,%2,%3};\n"
        : "+f"(c[0]), "+f"(c[1]), "+f"(c[2]), "+f"(c[3])
        : "r"(__float_as_uint(a[0])), "r"(__float_as_uint(a[1])),
          "r"(__float_as_uint(a[2])), "r"(__float_as_uint(a[3])),
          "r"(__float_as_uint(b[0])), "r"(__float_as_uint(b[1])));
}

__device__ __forceinline__ float tf32_hi(float v)
{
    return __uint_as_float(__float_as_uint(v) & 0xFFFFE000u);
}

// ---------------- tf32x3 GEMM: C[M,N] = A[M,K]@B[K,N] (+bias) --------------------
// 128x128 CTA tile, BK=16, 256 threads (8 warps, 4x2), warp tile 32x64.
// Software-pipelined: LDG for tile i+1 issued before compute of tile i;
// single __syncthreads per iteration. Requires K%16==0, N%128==0. M guarded.
// Accuracy: 3-pass tf32 (hi*hi + hi*lo + lo*hi) ~ fp32.
__global__ void __launch_bounds__(256) tf32gemm(
    const float* __restrict__ A, const float* __restrict__ Bm,
    const float* __restrict__ bias, float* __restrict__ C,
    int M, int N, int K, int lda, int ldb, int ldc)
{
    extern __shared__ float ts[];
    const int tid  = threadIdx.x;
    const int m0   = blockIdx.y * 128;
    const int n0   = blockIdx.x * 128;
    const int lane = tid & 31;
    const int warp = tid >> 5;
    const int gid  = lane >> 2;       // 0..7
    const int tig  = lane & 3;        // 0..3
    const int wm   = warp & 3;        // 32-row band
    const int wn   = warp >> 2;       // 64-col band

    // loader lane geometry (2 passes of 256 threads each)
    const int a_row0 = tid >> 2;            // rows: a_row0, a_row0+64
    const int a_kq   = (tid & 3) << 2;      // 0,4,8,12
    const int b_kk0  = tid >> 5;            // k rows: b_kk0, b_kk0+8
    const int b_nq   = (lane) << 2;         // 0..124

    float c[2][8][4];
#pragma unroll
    for (int i = 0; i < 2; i++)
#pragma unroll
        for (int j = 0; j < 8; j++)
#pragma unroll
            for (int e = 0; e < 4; e++) c[i][j][e] = 0.f;

    float4 aP[2], bP[2];

    // ---- tile loader: global -> regs ----
    auto load_tiles = [&](int k0) {
#pragma unroll
        for (int it = 0; it < 2; it++) {
            int row = a_row0 + it * 64;
            aP[it] = make_float4(0.f, 0.f, 0.f, 0.f);
            if (m0 + row < M)
                aP[it] = *reinterpret_cast<const float4*>(
                    &A[(size_t)(m0 + row) * lda + k0 + a_kq]);
        }
#pragma unroll
        for (int it = 0; it < 2; it++) {
            int kk = b_kk0 + it * 8;
            bP[it] = *reinterpret_cast<const float4*>(
                &Bm[(size_t)(k0 + kk) * ldb + n0 + b_nq]);
        }
    };

    // ---- tile storer: regs -> smem stage (with tf32 hi/lo split) ----
    auto store_tiles = [&](int stage) {
        float* As_h = ts + stage * TF_STAGE_TOT;
        float* As_l = As_h + TF_STAGE;
        float* Bs_h = As_l + TF_STAGE;
        float* Bs_l = Bs_h + TF_STAGE;
#pragma unroll
        for (int it = 0; it < 2; it++) {
            int row = a_row0 + it * 64;
            float vs[4] = {aP[it].x, aP[it].y, aP[it].z, aP[it].w};
#pragma unroll
            for (int j = 0; j < 4; j++) {
                float hi = tf32_hi(vs[j]);
                As_h[(a_kq + j) * TF_PAD + row] = hi;
                As_l[(a_kq + j) * TF_PAD + row] = vs[j] - hi;
            }
        }
#pragma unroll
        for (int it = 0; it < 2; it++) {
            int kk = b_kk0 + it * 8;
            float4 bv = bP[it];
            float4 hv, lv;
            hv.x = tf32_hi(bv.x); lv.x = bv.x - hv.x;
            hv.y = tf32_hi(bv.y); lv.y = bv.y - hv.y;
            hv.z = tf32_hi(bv.z); lv.z = bv.z - hv.z;
            hv.w = tf32_hi(bv.w); lv.w = bv.w - hv.w;
            *reinterpret_cast<float4*>(&Bs_h[kk * TF_PAD + b_nq]) = hv;
            *reinterpret_cast<float4*>(&Bs_l[kk * TF_PAD + b_nq]) = lv;
        }
    };

    // prologue
    load_tiles(0);
    store_tiles(0);
    __syncthreads();

    int cur = 0;
    for (int k0 = 0; k0 < K; k0 += 16) {
        const bool more = (k0 + 16) < K;
        if (more) load_tiles(k0 + 16);      // LDG in flight during mma

        const float* As_h = ts + cur * TF_STAGE_TOT;
        const float* As_l = As_h + TF_STAGE;
        const float* Bs_h = As_l + TF_STAGE;
        const float* Bs_l = Bs_h + TF_STAGE;

#pragma unroll
        for (int k8 = 0; k8 < 2; k8++) {
            const int kb = k8 * 8;
            float ah[2][4], al[2][4];
#pragma unroll
            for (int mt = 0; mt < 2; mt++) {
                int rb = wm * 32 + mt * 16;
                ah[mt][0] = As_h[(kb + tig) * TF_PAD + rb + gid];
                ah[mt][1] = As_h[(kb + tig) * TF_PAD + rb + gid + 8];
                ah[mt][2] = As_h[(kb + tig + 4) * TF_PAD + rb + gid];
                ah[mt][3] = As_h[(kb + tig + 4) * TF_PAD + rb + gid + 8];
                al[mt][0] = As_l[(kb + tig) * TF_PAD + rb + gid];
                al[mt][1] = As_l[(kb + tig) * TF_PAD + rb + gid + 8];
                al[mt][2] = As_l[(kb + tig + 4) * TF_PAD + rb + gid];
                al[mt][3] = As_l[(kb + tig + 4) * TF_PAD + rb + gid + 8];
            }
#pragma unroll
            for (int nt = 0; nt < 8; nt++) {
                int cb = wn * 64 + nt * 8;
                float bh[2], bl[2];
                bh[0] = Bs_h[(kb + tig) * TF_PAD + cb + gid];
                bh[1] = Bs_h[(kb + tig + 4) * TF_PAD + cb + gid];
                bl[0] = Bs_l[(kb + tig) * TF_PAD + cb + gid];
                bl[1] = Bs_l[(kb + tig + 4) * TF_PAD + cb + gid];
#pragma unroll
                for (int mt = 0; mt < 2; mt++) {
                    mma_tf32(c[mt][nt], ah[mt], bh);   // hi*hi
                    mma_tf32(c[mt][nt], ah[mt], bl);   // hi*lo
                    mma_tf32(c[mt][nt], al[mt], bh);   // lo*hi
                }
            }
        }

        if (more) {
            store_tiles(cur ^ 1);
            __syncthreads();
            cur ^= 1;
        }
    }

    // ---- epilogue: bias + store (float2 per fragment row) ----
#pragma unroll
    for (int mt = 0; mt < 2; mt++) {
#pragma unroll
        for (int nt = 0; nt < 8; nt++) {
            int col = n0 + wn * 64 + nt * 8 + tig * 2;
            float bx = 0.f, by = 0.f;
            if (bias) { bx = bias[col]; by = bias[col + 1]; }
            int row0 = m0 + wm * 32 + mt * 16 + gid;
            if (row0 < M) {
                float2 v = make_float2(c[mt][nt][0] + bx, c[mt][nt][1] + by);
                *reinterpret_cast<float2*>(&C[(size_t)row0 * ldc + col]) = v;
            }
            int row1 = row0 + 8;
            if (row1 < M) {
                float2 v = make_float2(c[mt][nt][2] + bx, c[mt][nt][3] + by);
                *reinterpret_cast<float2*>(&C[(size_t)row1 * ldc + col]) = v;
            }
        }
    }
}

// ---------------- fp32 GEMM (prep-only; exact path for fused weights) ------------
__global__ void __launch_bounds__(256) sgemm128(
    const float* __restrict__ A, const float* __restrict__ Bm,
    const float* __restrict__ bias, float* __restrict__ C,
    int M, int N, int K, int lda, int ldb, int ldc)
{
    __shared__ float As[2][8][128];
    __shared__ float Bs[2][8][128];

    const int tid = threadIdx.x;
    const int m0 = blockIdx.y * 128;
    const int n0 = blockIdx.x * 128;

    const int ar = tid >> 1;
    const int ak = (tid & 1) * 4;
    const int br = tid >> 5;
    const int bn = (tid & 31) * 4;
    const int tx = tid & 15;
    const int ty = tid >> 4;

    float acc[8][8];
#pragma unroll
    for (int i = 0; i < 8; i++)
#pragma unroll
        for (int j = 0; j < 8; j++) acc[i][j] = 0.f;

    float4 av = make_float4(0.f, 0.f, 0.f, 0.f);
    if (m0 + ar < M)
        av = *reinterpret_cast<const float4*>(&A[(size_t)(m0 + ar) * lda + ak]);
    float4 bv = *reinterpret_cast<const float4*>(&Bm[(size_t)br * ldb + n0 + bn]);
    As[0][ak + 0][ar] = av.x;
    As[0][ak + 1][ar] = av.y;
    As[0][ak + 2][ar] = av.z;
    As[0][ak + 3][ar] = av.w;
    *reinterpret_cast<float4*>(&Bs[0][br][bn]) = bv;
    __syncthreads();

    int buf = 0;
    for (int k0 = 0; k0 < K; k0 += 8) {
        const bool more = (k0 + 8) < K;
        float4 av2, bv2;
        if (more) {
            av2 = make_float4(0.f, 0.f, 0.f, 0.f);
            if (m0 + ar < M)
                av2 = *reinterpret_cast<const float4*>(&A[(size_t)(m0 + ar) * lda + k0 + 8 + ak]);
            bv2 = *reinterpret_cast<const float4*>(&Bm[(size_t)(k0 + 8 + br) * ldb + n0 + bn]);
        }
#pragma unroll
        for (int kk = 0; kk < 8; kk++) {
            float4 a0 = *reinterpret_cast<const float4*>(&As[buf][kk][ty * 4]);
            float4 a1 = *reinterpret_cast<const float4*>(&As[buf][kk][64 + ty * 4]);
            float4 b0 = *reinterpret_cast<const float4*>(&Bs[buf][kk][tx * 4]);
            float4 b1 = *reinterpret_cast<const float4*>(&Bs[buf][kk][64 + tx * 4]);
            float a[8] = {a0.x, a0.y, a0.z, a0.w, a1.x, a1.y, a1.z, a1.w};
            float b[8] = {b0.x, b0.y, b0.z, b0.w, b1.x, b1.y, b1.z, b1.w};
#pragma unroll
            for (int i = 0; i < 8; i++)
#pragma unroll
                for (int j = 0; j < 8; j++) acc[i][j] += a[i] * b[j];
        }
        if (more) {
            buf ^= 1;
            As[buf][ak + 0][ar] = av2.x;
            As[buf][ak + 1][ar] = av2.y;
            As[buf][ak + 2][ar] = av2.z;
            As[buf][ak + 3][ar] = av2.w;
            *reinterpret_cast<float4*>(&Bs[buf][br][bn]) = bv2;
            __syncthreads();
        }
    }

#pragma unroll
    for (int i = 0; i < 8; i++) {
        int m = m0 + ((i < 4) ? (ty * 4 + i) : (64 + ty * 4 + i - 4));
        if (m >= M) continue;
#pragma unroll
        for (int jh = 0; jh < 2; jh++) {
            int n = n0 + jh * 64 + tx * 4;
            float4 v;
            v.x = acc[i][jh * 4 + 0];
            v.y = acc[i][jh * 4 + 1];
            v.z = acc[i][jh * 4 + 2];
            v.w = acc[i][jh * 4 + 3];
            if (bias) {
                v.x += bias[n + 0]; v.y += bias[n + 1];
                v.z += bias[n + 2]; v.w += bias[n + 3];
            }
            *reinterpret_cast<float4*>(&C[(size_t)m * ldc + n]) = v;
        }
    }
}

// ---------------- BatchNorm (train, biased var) + ELU, in place ------------------
__global__ void bn_elu_kernel(float* __restrict__ X,
                              const float* __restrict__ gamma,
                              const float* __restrict__ beta)
{
    const int t = blockIdx.x;
    const int j = blockIdx.y * 128 + threadIdx.x;
    float s = 0.f, ss = 0.f;
    for (int b = 0; b < B_; b++) {
        float v = X[(size_t)(b * T_ + t) * H1_ + j];
        s += v; ss += v * v;
    }
    float mu  = s * (1.f / B_);
    float var = ss * (1.f / B_) - mu * mu;
    float sc  = gamma[j] * rsqrtf(var + 1e-5f);
    float sh  = beta[j] - mu * sc;
    for (int b = 0; b < B_; b++) {
        size_t idx = (size_t)(b * T_ + t) * H1_ + j;
        float y = X[idx] * sc + sh;
        X[idx] = (y > 0.f) ? y : expm1f(y);   // ELU alpha=1
    }
}

// ---------------- action encoder: AENC = actions @ Wae + bae --------------------
__global__ void aenc_kernel(const float* __restrict__ act,
                            const float* __restrict__ Wae,
                            const float* __restrict__ bae)
{
    int idx = blockIdx.x * blockDim.x + threadIdx.x;
    if (idx >= BT_ * A_) return;
    int r = idx >> 4, j = idx & 15;
    float acc = bae[j];
#pragma unroll
    for (int k = 0; k < 16; k++) acc += act[(r << 4) + k] * Wae[(k << 4) + j];
    g_AENC[idx] = acc;
}

// ---------------- weight-fusion prep ---------------------------------------------
__global__ void prep_bias_kernel(const float* __restrict__ b3,
                                 const float* __restrict__ bih,
                                 const float* __restrict__ Wih,
                                 const float* __restrict__ bhe,
                                 const float* __restrict__ bhh,
                                 const float* __restrict__ Whh)
{
    int j = blockIdx.x * blockDim.x + threadIdx.x;
    if (j < G3_) {
        float a1 = bih[j], a2 = bhh[j];
        for (int k = 0; k < E_; k++) {
            a1 += b3[k]  * Wih[k * G3_ + j];
            a2 += bhe[k] * Whh[k * G3_ + j];
        }
        g_b34v[j] = a1;
        g_bstep[E_ + j] = a2;
    }
    if (j < E_) g_bstep[j] = bhe[j];
}

__global__ void prep_whe_copy(const float* __restrict__ Whe)
{
    int idx = blockIdx.x * blockDim.x + threadIdx.x;
    if (idx >= CAT_ * E_) return;
    int i = idx / E_, j = idx - i * E_;
    g_Wstep[i * SN_ + j] = Whe[idx];
}

// zero h0 + reset grid barrier (runs every graph replay, before phase B)
__global__ void zero_kernel(float* p, int n)
{
    int i = blockIdx.x * blockDim.x + threadIdx.x;
    if (i == 0) g_bar = 0u;
    if (i < n) p[i] = 0.f;
}

// ---------------- phase B: persistent recurrence kernel --------------------------
// 128 CTAs (8 j-tiles x 16 b-tiles), 256 threads, 1 CTA/SM. Wstep slice resident
// in smem for all 128 steps. Hidden state read with __ldcg (L1 is stale across
// the software grid barrier; only L2 is coherent between SMs within one launch).
__global__ void __launch_bounds__(256) phaseB_kernel(
    float* __restrict__ Ha, float* __restrict__ Hb,
    const float* __restrict__ aenc, const float* __restrict__ GI,
    float* __restrict__ out)
{
    extern __shared__ float sm[];
    float* Bs = sm;                 // [CAT_][BS_STRIDE], 128 gathered cols
    float* As = sm + OFF_AS;        // [CAT_][AS_STRIDE], 16 batch rows
    float* Ys = sm + OFF_YS;        // [16][BS_STRIDE]

    const int tid = threadIdx.x;
    const int j0 = blockIdx.x * 32;
    const int b0 = blockIdx.y * 16;
    const int tx = tid & 31;
    const int ty = tid >> 5;

    for (int i = tid; i < CAT_ * 128; i += 256) {
        int k = i >> 7;
        int c = i & 127;
        int g = c >> 5;
        Bs[k * BS_STRIDE + c] = g_Wstep[k * SN_ + g * E_ + j0 + (c & 31)];
    }

    float bias_c[4];
#pragma unroll
    for (int q = 0; q < 4; q++) {
        int c = tx * 4 + q;
        int g = c >> 5;
        bias_c[q] = g_bstep[g * E_ + j0 + (c & 31)];
    }
    __syncthreads();

    float* hin = Ha;
    float* hout = Hb;

    for (int t = 0; t < T_; t++) {
        for (int i = tid; i < 16 * 256; i += 256) {
            int row = i >> 8, k = i & 255;
            As[k * AS_STRIDE + row] = __ldcg(&hin[(b0 + row) * E_ + k]);
        }
        {
            int row = tid >> 4, k2 = tid & 15;
            float v = 0.f;
            if (t > 0)
                v = aenc[((size_t)(b0 + row) * T_ + (t - 1)) * A_ + k2];
            As[(E_ + k2) * AS_STRIDE + row] = v;
        }
        __syncthreads();

        float acc0[4] = {0.f, 0.f, 0.f, 0.f};
        float acc1[4] = {0.f, 0.f, 0.f, 0.f};
#pragma unroll 4
        for (int k = 0; k < CAT_; k++) {
            float a0 = As[k * AS_STRIDE + ty];
            float a1 = As[k * AS_STRIDE + ty + 8];
            float4 b4 = *reinterpret_cast<const float4*>(&Bs[k * BS_STRIDE + tx * 4]);
            acc0[0] += a0 * b4.x; acc0[1] += a0 * b4.y;
            acc0[2] += a0 * b4.z; acc0[3] += a0 * b4.w;
            acc1[0] += a1 * b4.x; acc1[1] += a1 * b4.y;
            acc1[2] += a1 * b4.z; acc1[3] += a1 * b4.w;
        }

#pragma unroll
        for (int q = 0; q < 4; q++) {
            int c = tx * 4 + q;
            Ys[ty * BS_STRIDE + c]       = acc0[q] + bias_c[q];
            Ys[(ty + 8) * BS_STRIDE + c] = acc1[q] + bias_c[q];
        }
        __syncthreads();

        float* o = (t == T_ - 1) ? out : hout;
#pragma unroll
        for (int q = 0; q < 2; q++) {
            int oidx = tid * 2 + q;
            int rr = oidx >> 5;
            int jl = oidx & 31;
            int b = b0 + rr;
            int j = j0 + jl;
            float henc = Ys[rr * BS_STRIDE + jl];
            float ghr  = Ys[rr * BS_STRIDE + 32 + jl];
            float ghz  = Ys[rr * BS_STRIDE + 64 + jl];
            float ghn  = Ys[rr * BS_STRIDE + 96 + jl];
            size_t gb = ((size_t)b * T_ + t) * G3_ + j;
            float ir  = GI[gb];
            float iz  = GI[gb + E_];
            float inn = GI[gb + 2 * E_];
            float r = 1.f / (1.f + expf(-(ir + ghr)));
            float z = 1.f / (1.f + expf(-(iz + ghz)));
            float nn = tanhf(inn + r * ghn);
            o[b * E_ + j] = (1.f - z) * nn + z * henc;
        }

        __threadfence();
        __syncthreads();
        if (tid == 0) {
            atomicAdd(&g_bar, 1u);
            const unsigned target = (unsigned)NB_CTAS * (unsigned)(t + 1);
            while (*((volatile unsigned*)&g_bar) < target)
                __nanosleep(40);
            __threadfence();
        }
        __syncthreads();

        float* tmp = hin; hin = hout; hout = tmp;
    }
}

// ---------------- host orchestration ---------------------------------------------
extern "C" void kernel_launch(void* const* d_in, const int* in_sizes, int n_in,
                              void* d_out, int out_size)
{
    const float* obs = (const float*)d_in[0];
    const float* act = (const float*)d_in[1];
    const float* W1  = (const float*)d_in[2];
    const float* b1  = (const float*)d_in[3];
    const float* g1  = (const float*)d_in[4];
    const float* be1 = (const float*)d_in[5];
    const float* W2  = (const float*)d_in[6];
    const float* b2  = (const float*)d_in[7];
    const float* g2  = (const float*)d_in[8];
    const float* be2 = (const float*)d_in[9];
    const float* W3  = (const float*)d_in[10];
    const float* b3  = (const float*)d_in[11];
    const float* Wih = (const float*)d_in[12];
    const float* bih = (const float*)d_in[13];
    const float* Whh = (const float*)d_in[14];
    const float* bhh = (const float*)d_in[15];
    const float* Whe = (const float*)d_in[16];
    const float* bhe = (const float*)d_in[17];
    const float* Wae = (const float*)d_in[18];
    const float* bae = (const float*)d_in[19];
    float* out = (float*)d_out;

    float *X1p, *X2p, *GIp, *AEp, *W34p, *b34p, *Wstepp, *Hap, *Hbp;
    cudaGetSymbolAddress((void**)&X1p,   g_X1);
    cudaGetSymbolAddress((void**)&X2p,   g_X2);
    cudaGetSymbolAddress((void**)&GIp,   g_GI);
    cudaGetSymbolAddress((void**)&AEp,   g_AENC);
    cudaGetSymbolAddress((void**)&W34p,  g_W34);
    cudaGetSymbolAddress((void**)&b34p,  g_b34v);
    cudaGetSymbolAddress((void**)&Wstepp,g_Wstep);
    cudaGetSymbolAddress((void**)&Hap,   g_Ha);
    cudaGetSymbolAddress((void**)&Hbp,   g_Hb);

    // opt-in smem sizes (idempotent)
    cudaFuncSetAttribute(phaseB_kernel,
                         cudaFuncAttributeMaxDynamicSharedMemorySize, SMEM_B_BYTES);
    cudaFuncSetAttribute(tf32gemm,
                         cudaFuncAttributeMaxDynamicSharedMemorySize, TF_SMEM_BYTES);

    // ---- prep + phase A, ordered so launch #4 = the big obs@W1 tf32gemm ----
    // (profiler slot lands on launch #4: profile the kernel that matters)
    prep_bias_kernel<<<3, 256>>>(b3, bih, Wih, bhe, bhh, Whh);         // 1
    prep_whe_copy<<<(CAT_ * E_ + 255) / 256, 256>>>(Whe);              // 2
    zero_kernel<<<(B_ * E_ + 255) / 256, 256>>>(Hap, B_ * E_);         // 3
    // X1 = obs @ W1 + b1  (independent of preps)
    tf32gemm<<<dim3(H1_ / 128, BT_ / 128), 256, TF_SMEM_BYTES>>>(      // 4
        obs, W1, b1, X1p, BT_, H1_, NIN_, NIN_, H1_, H1_);
    // W34 = W3 @ Wih   [512,768], K=256
    sgemm128<<<dim3(G3_ / 128, (H1_ + 127) / 128), 256>>>(             // 5
        W3, Wih, nullptr, W34p, H1_, G3_, E_, E_, G3_, G3_);
    // Wstep[:, 256:1024] = Whe @ Whh
    sgemm128<<<dim3(G3_ / 128, (CAT_ + 127) / 128), 256>>>(            // 6
        Whe, Whh, nullptr, Wstepp + E_, CAT_, G3_, E_, E_, G3_, SN_);
    bn_elu_kernel<<<dim3(T_, H1_ / 128), 128>>>(X1p, g1, be1);         // 7
    tf32gemm<<<dim3(H1_ / 128, BT_ / 128), 256, TF_SMEM_BYTES>>>(      // 8
        X1p, W2, b2, X2p, BT_, H1_, H1_, H1_, H1_, H1_);
    bn_elu_kernel<<<dim3(T_, H1_ / 128), 128>>>(X2p, g2, be2);         // 9
    tf32gemm<<<dim3(G3_ / 128, BT_ / 128), 256, TF_SMEM_BYTES>>>(      // 10
        X2p, W34p, b34p, GIp, BT_, G3_, H1_, H1_, G3_, G3_);
    aenc_kernel<<<(BT_ * A_ + 255) / 256, 256>>>(act, Wae, bae);       // 11

    // ---- phase B: one persistent kernel, 128 steps, grid barrier per step ----
    phaseB_kernel<<<dim3(8, 16), 256, SMEM_B_BYTES>>>(Hap, Hbp, AEp, GIp, out);
}

// round 13
// speedup vs baseline: 1.1354x; 1.0449x over previous
#include <cuda_runtime.h>
#include <math.h>
#include <stdint.h>

// Problem constants
#define B_    256
#define T_    128
#define BT_   32768
#define NIN_  1024
#define H1_   512
#define E_    256
#define G3_   768      // 3*E
#define A_    16
#define CAT_  272      // E + A
#define SN_   1024     // step GEMM N = E (h_enc) + 3E (gh)
#define NB_CTAS 128    // phase-B grid (8 x 16)

// phase-B dynamic smem layout (floats)
#define BS_STRIDE 132
#define AS_STRIDE 17
#define OFF_AS    (CAT_ * BS_STRIDE)
#define OFF_YS    (OFF_AS + CAT_ * AS_STRIDE)
#define SMEM_B_FLOATS (OFF_YS + 16 * BS_STRIDE)
#define SMEM_B_BYTES  (SMEM_B_FLOATS * 4)

// tf32 GEMM smem layout (floats)
#define TF_PAD        136                   // 136 mod 32 == 8 -> conflict-free frags
#define TF_STAGE      (16 * TF_PAD)         // 2176 floats per array
#define TF_STAGE_TOT  (4 * TF_STAGE)        // As_hi | As_lo | Bs_hi | Bs_lo
#define TF_SMEM_FLOATS (2 * TF_STAGE_TOT)   // double-buffered
#define TF_SMEM_BYTES  (TF_SMEM_FLOATS * 4) // 69632 B; x2 CTAs = 139 KB < 228 KB

// ---------------- scratch (device globals; no allocation allowed) ----------------
__device__ float g_X1[BT_ * H1_];
__device__ float g_X2[BT_ * H1_];
__device__ float g_GI[BT_ * G3_];
__device__ float g_AENC[BT_ * A_];
__device__ float g_W34[H1_ * G3_];
__device__ float g_b34v[G3_];
__device__ float g_Wstep[CAT_ * SN_];      // [Whe | Whe@Whh]
__device__ float g_bstep[SN_];             // [bhe | bhe@Whh + bhh]
__device__ float g_Ha[B_ * E_];
__device__ float g_Hb[B_ * E_];
__device__ unsigned g_bar;

// ---------------- tf32 mma helper ------------------------------------------------
__device__ __forceinline__ void mma_tf32(float (&c)[4], const float (&a)[4],
                                         const float (&b)[2])
{
    asm volatile(
        "mma.sync.aligned.m16n8k8.row.col.f32.tf32.tf32.f32 "
        "{%0,%1,%2,%3}, {%4,%5,%6,%7}, {%8,%9}, {%0,%1,%2,%3};\n"
        : "+f"(c[0]), "+f"(c[1]), "+f"(c[2]), "+f"(c[3])
        : "r"(__float_as_uint(a[0])), "r"(__float_as_uint(a[1])),
          "r"(__float_as_uint(a[2])), "r"(__float_as_uint(a[3])),
          "r"(__float_as_uint(b[0])), "r"(__float_as_uint(b[1])));
}

__device__ __forceinline__ float tf32_hi(float v)
{
    return __uint_as_float(__float_as_uint(v) & 0xFFFFE000u);
}

// ---------------- tf32x3 GEMM: C[M,N] = A[M,K]@B[K,N] (+bias) --------------------
// 128x128 CTA tile, BK=16, 256 threads (8 warps, 4x2), warp tile 32x64.
// Software-pipelined; single __syncthreads per iteration. K%16==0, N%128==0.
// __launch_bounds__(256, 2): cap regs at 128 so two CTAs co-reside per SM.
__global__ void __launch_bounds__(256, 2) tf32gemm(
    const float* __restrict__ A, const float* __restrict__ Bm,
    const float* __restrict__ bias, float* __restrict__ C,
    int M, int N, int K, int lda, int ldb, int ldc)
{
    extern __shared__ float ts[];
    const int tid  = threadIdx.x;
    const int m0   = blockIdx.y * 128;
    const int n0   = blockIdx.x * 128;
    const int lane = tid & 31;
    const int warp = tid >> 5;
    const int gid  = lane >> 2;       // 0..7
    const int tig  = lane & 3;        // 0..3
    const int wm   = warp & 3;        // 32-row band
    const int wn   = warp >> 2;       // 64-col band

    const int a_row0 = tid >> 2;            // rows: a_row0, a_row0+64
    const int a_kq   = (tid & 3) << 2;      // 0,4,8,12
    const int b_kk0  = tid >> 5;            // k rows: b_kk0, b_kk0+8
    const int b_nq   = (lane) << 2;         // 0..124

    float c[2][8][4];
#pragma unroll
    for (int i = 0; i < 2; i++)
#pragma unroll
        for (int j = 0; j < 8; j++)
#pragma unroll
            for (int e = 0; e < 4; e++) c[i][j][e] = 0.f;

    float4 aP[2], bP[2];

    auto load_tiles = [&](int k0) {
#pragma unroll
        for (int it = 0; it < 2; it++) {
            int row = a_row0 + it * 64;
            aP[it] = make_float4(0.f, 0.f, 0.f, 0.f);
            if (m0 + row < M)
                aP[it] = *reinterpret_cast<const float4*>(
                    &A[(size_t)(m0 + row) * lda + k0 + a_kq]);
        }
#pragma unroll
        for (int it = 0; it < 2; it++) {
            int kk = b_kk0 + it * 8;
            bP[it] = *reinterpret_cast<const float4*>(
                &Bm[(size_t)(k0 + kk) * ldb + n0 + b_nq]);
        }
    };

    auto store_tiles = [&](int stage) {
        float* As_h = ts + stage * TF_STAGE_TOT;
        float* As_l = As_h + TF_STAGE;
        float* Bs_h = As_l + TF_STAGE;
        float* Bs_l = Bs_h + TF_STAGE;
#pragma unroll
        for (int it = 0; it < 2; it++) {
            int row = a_row0 + it * 64;
            float vs[4] = {aP[it].x, aP[it].y, aP[it].z, aP[it].w};
#pragma unroll
            for (int j = 0; j < 4; j++) {
                float hi = tf32_hi(vs[j]);
                As_h[(a_kq + j) * TF_PAD + row] = hi;
                As_l[(a_kq + j) * TF_PAD + row] = vs[j] - hi;
            }
        }
#pragma unroll
        for (int it = 0; it < 2; it++) {
            int kk = b_kk0 + it * 8;
            float4 bv = bP[it];
            float4 hv, lv;
            hv.x = tf32_hi(bv.x); lv.x = bv.x - hv.x;
            hv.y = tf32_hi(bv.y); lv.y = bv.y - hv.y;
            hv.z = tf32_hi(bv.z); lv.z = bv.z - hv.z;
            hv.w = tf32_hi(bv.w); lv.w = bv.w - hv.w;
            *reinterpret_cast<float4*>(&Bs_h[kk * TF_PAD + b_nq]) = hv;
            *reinterpret_cast<float4*>(&Bs_l[kk * TF_PAD + b_nq]) = lv;
        }
    };

    load_tiles(0);
    store_tiles(0);
    __syncthreads();

    int cur = 0;
    for (int k0 = 0; k0 < K; k0 += 16) {
        const bool more = (k0 + 16) < K;
        if (more) load_tiles(k0 + 16);      // LDG in flight during mma

        const float* As_h = ts + cur * TF_STAGE_TOT;
        const float* As_l = As_h + TF_STAGE;
        const float* Bs_h = As_l + TF_STAGE;
        const float* Bs_l = Bs_h + TF_STAGE;

#pragma unroll
        for (int k8 = 0; k8 < 2; k8++) {
            const int kb = k8 * 8;
            float ah[2][4], al[2][4];
#pragma unroll
            for (int mt = 0; mt < 2; mt++) {
                int rb = wm * 32 + mt * 16;
                ah[mt][0] = As_h[(kb + tig) * TF_PAD + rb + gid];
                ah[mt][1] = As_h[(kb + tig) * TF_PAD + rb + gid + 8];
                ah[mt][2] = As_h[(kb + tig + 4) * TF_PAD + rb + gid];
                ah[mt][3] = As_h[(kb + tig + 4) * TF_PAD + rb + gid + 8];
                al[mt][0] = As_l[(kb + tig) * TF_PAD + rb + gid];
                al[mt][1] = As_l[(kb + tig) * TF_PAD + rb + gid + 8];
                al[mt][2] = As_l[(kb + tig + 4) * TF_PAD + rb + gid];
                al[mt][3] = As_l[(kb + tig + 4) * TF_PAD + rb + gid + 8];
            }
#pragma unroll
            for (int nt = 0; nt < 8; nt++) {
                int cb = wn * 64 + nt * 8;
                float bh[2], bl[2];
                bh[0] = Bs_h[(kb + tig) * TF_PAD + cb + gid];
                bh[1] = Bs_h[(kb + tig + 4) * TF_PAD + cb + gid];
                bl[0] = Bs_l[(kb + tig) * TF_PAD + cb + gid];
                bl[1] = Bs_l[(kb + tig + 4) * TF_PAD + cb + gid];
#pragma unroll
                for (int mt = 0; mt < 2; mt++) {
                    mma_tf32(c[mt][nt], ah[mt], bh);   // hi*hi
                    mma_tf32(c[mt][nt], ah[mt], bl);   // hi*lo
                    mma_tf32(c[mt][nt], al[mt], bh);   // lo*hi
                }
            }
        }

        if (more) {
            store_tiles(cur ^ 1);
            __syncthreads();
            cur ^= 1;
        }
    }

    // ---- epilogue: bias + store ----
#pragma unroll
    for (int mt = 0; mt < 2; mt++) {
#pragma unroll
        for (int nt = 0; nt < 8; nt++) {
            int col = n0 + wn * 64 + nt * 8 + tig * 2;
            float bx = 0.f, by = 0.f;
            if (bias) { bx = bias[col]; by = bias[col + 1]; }
            int row0 = m0 + wm * 32 + mt * 16 + gid;
            if (row0 < M) {
                float2 v = make_float2(c[mt][nt][0] + bx, c[mt][nt][1] + by);
                *reinterpret_cast<float2*>(&C[(size_t)row0 * ldc + col]) = v;
            }
            int row1 = row0 + 8;
            if (row1 < M) {
                float2 v = make_float2(c[mt][nt][2] + bx, c[mt][nt][3] + by);
                *reinterpret_cast<float2*>(&C[(size_t)row1 * ldc + col]) = v;
            }
        }
    }
}

// ---------------- fp32 GEMM (prep-only; exact path for fused weights) ------------
__global__ void __launch_bounds__(256) sgemm128(
    const float* __restrict__ A, const float* __restrict__ Bm,
    const float* __restrict__ bias, float* __restrict__ C,
    int M, int N, int K, int lda, int ldb, int ldc)
{
    __shared__ float As[2][8][128];
    __shared__ float Bs[2][8][128];

    const int tid = threadIdx.x;
    const int m0 = blockIdx.y * 128;
    const int n0 = blockIdx.x * 128;

    const int ar = tid >> 1;
    const int ak = (tid & 1) * 4;
    const int br = tid >> 5;
    const int bn = (tid & 31) * 4;
    const int tx = tid & 15;
    const int ty = tid >> 4;

    float acc[8][8];
#pragma unroll
    for (int i = 0; i < 8; i++)
#pragma unroll
        for (int j = 0; j < 8; j++) acc[i][j] = 0.f;

    float4 av = make_float4(0.f, 0.f, 0.f, 0.f);
    if (m0 + ar < M)
        av = *reinterpret_cast<const float4*>(&A[(size_t)(m0 + ar) * lda + ak]);
    float4 bv = *reinterpret_cast<const float4*>(&Bm[(size_t)br * ldb + n0 + bn]);
    As[0][ak + 0][ar] = av.x;
    As[0][ak + 1][ar] = av.y;
    As[0][ak + 2][ar] = av.z;
    As[0][ak + 3][ar] = av.w;
    *reinterpret_cast<float4*>(&Bs[0][br][bn]) = bv;
    __syncthreads();

    int buf = 0;
    for (int k0 = 0; k0 < K; k0 += 8) {
        const bool more = (k0 + 8) < K;
        float4 av2, bv2;
        if (more) {
            av2 = make_float4(0.f, 0.f, 0.f, 0.f);
            if (m0 + ar < M)
                av2 = *reinterpret_cast<const float4*>(&A[(size_t)(m0 + ar) * lda + k0 + 8 + ak]);
            bv2 = *reinterpret_cast<const float4*>(&Bm[(size_t)(k0 + 8 + br) * ldb + n0 + bn]);
        }
#pragma unroll
        for (int kk = 0; kk < 8; kk++) {
            float4 a0 = *reinterpret_cast<const float4*>(&As[buf][kk][ty * 4]);
            float4 a1 = *reinterpret_cast<const float4*>(&As[buf][kk][64 + ty * 4]);
            float4 b0 = *reinterpret_cast<const float4*>(&Bs[buf][kk][tx * 4]);
            float4 b1 = *reinterpret_cast<const float4*>(&Bs[buf][kk][64 + tx * 4]);
            float a[8] = {a0.x, a0.y, a0.z, a0.w, a1.x, a1.y, a1.z, a1.w};
            float b[8] = {b0.x, b0.y, b0.z, b0.w, b1.x, b1.y, b1.z, b1.w};
#pragma unroll
            for (int i = 0; i < 8; i++)
#pragma unroll
                for (int j = 0; j < 8; j++) acc[i][j] += a[i] * b[j];
        }
        if (more) {
            buf ^= 1;
            As[buf][ak + 0][ar] = av2.x;
            As[buf][ak + 1][ar] = av2.y;
            As[buf][ak + 2][ar] = av2.z;
            As[buf][ak + 3][ar] = av2.w;
            *reinterpret_cast<float4*>(&Bs[buf][br][bn]) = bv2;
            __syncthreads();
        }
    }

#pragma unroll
    for (int i = 0; i < 8; i++) {
        int m = m0 + ((i < 4) ? (ty * 4 + i) : (64 + ty * 4 + i - 4));
        if (m >= M) continue;
#pragma unroll
        for (int jh = 0; jh < 2; jh++) {
            int n = n0 + jh * 64 + tx * 4;
            float4 v;
            v.x = acc[i][jh * 4 + 0];
            v.y = acc[i][jh * 4 + 1];
            v.z = acc[i][jh * 4 + 2];
            v.w = acc[i][jh * 4 + 3];
            if (bias) {
                v.x += bias[n + 0]; v.y += bias[n + 1];
                v.z += bias[n + 2]; v.w += bias[n + 3];
            }
            *reinterpret_cast<float4*>(&C[(size_t)m * ldc + n]) = v;
        }
    }
}

// ---------------- BatchNorm (train, biased var) + ELU, in place ------------------
__global__ void bn_elu_kernel(float* __restrict__ X,
                              const float* __restrict__ gamma,
                              const float* __restrict__ beta)
{
    const int t = blockIdx.x;
    const int j = blockIdx.y * 128 + threadIdx.x;
    float s = 0.f, ss = 0.f;
    for (int b = 0; b < B_; b++) {
        float v = X[(size_t)(b * T_ + t) * H1_ + j];
        s += v; ss += v * v;
    }
    float mu  = s * (1.f / B_);
    float var = ss * (1.f / B_) - mu * mu;
    float sc  = gamma[j] * rsqrtf(var + 1e-5f);
    float sh  = beta[j] - mu * sc;
    for (int b = 0; b < B_; b++) {
        size_t idx = (size_t)(b * T_ + t) * H1_ + j;
        float y = X[idx] * sc + sh;
        X[idx] = (y > 0.f) ? y : expm1f(y);   // ELU alpha=1
    }
}

// ---------------- action encoder: AENC = actions @ Wae + bae --------------------
__global__ void aenc_kernel(const float* __restrict__ act,
                            const float* __restrict__ Wae,
                            const float* __restrict__ bae)
{
    int idx = blockIdx.x * blockDim.x + threadIdx.x;
    if (idx >= BT_ * A_) return;
    int r = idx >> 4, j = idx & 15;
    float acc = bae[j];
#pragma unroll
    for (int k = 0; k < 16; k++) acc += act[(r << 4) + k] * Wae[(k << 4) + j];
    g_AENC[idx] = acc;
}

// ---------------- weight-fusion prep ---------------------------------------------
__global__ void prep_bias_kernel(const float* __restrict__ b3,
                                 const float* __restrict__ bih,
                                 const float* __restrict__ Wih,
                                 const float* __restrict__ bhe,
                                 const float* __restrict__ bhh,
                                 const float* __restrict__ Whh)
{
    int j = blockIdx.x * blockDim.x + threadIdx.x;
    if (j < G3_) {
        float a1 = bih[j], a2 = bhh[j];
        for (int k = 0; k < E_; k++) {
            a1 += b3[k]  * Wih[k * G3_ + j];
            a2 += bhe[k] * Whh[k * G3_ + j];
        }
        g_b34v[j] = a1;
        g_bstep[E_ + j] = a2;
    }
    if (j < E_) g_bstep[j] = bhe[j];
}

__global__ void prep_whe_copy(const float* __restrict__ Whe)
{
    int idx = blockIdx.x * blockDim.x + threadIdx.x;
    if (idx >= CAT_ * E_) return;
    int i = idx / E_, j = idx - i * E_;
    g_Wstep[i * SN_ + j] = Whe[idx];
}

// zero h0 + reset grid barrier (runs every graph replay, before phase B)
__global__ void zero_kernel(float* p, int n)
{
    int i = blockIdx.x * blockDim.x + threadIdx.x;
    if (i == 0) g_bar = 0u;
    if (i < n) p[i] = 0.f;
}

// ---------------- phase B: persistent recurrence kernel --------------------------
// 128 CTAs (8 j-tiles x 16 b-tiles), 256 threads, 1 CTA/SM. Wstep slice resident
// in smem. NEW compute mapping: warp w owns cols [w*16, w*16+16); lane = (cg=l&3
// -> 4 cols, rg=l>>2 -> rows 2rg,2rg+1). Per k a warp touches only 4 distinct B
// float4s (8-lane broadcast, ~free) and 8 broadcast A scalars -> B crossbar
// traffic drops 8x vs the old tx-spread mapping; per-output accumulation order
// is unchanged (bit-identical results). Hidden state read with __ldcg (L1 is
// stale across the software grid barrier; only L2 is coherent intra-launch).
__global__ void __launch_bounds__(256) phaseB_kernel(
    float* __restrict__ Ha, float* __restrict__ Hb,
    const float* __restrict__ aenc, const float* __restrict__ GI,
    float* __restrict__ out)
{
    extern __shared__ float sm[];
    float* Bs = sm;                 // [CAT_][BS_STRIDE], 128 gathered cols
    float* As = sm + OFF_AS;        // [CAT_][AS_STRIDE], 16 batch rows
    float* Ys = sm + OFF_YS;        // [16][BS_STRIDE]

    const int tid = threadIdx.x;
    const int j0 = blockIdx.x * 32;
    const int b0 = blockIdx.y * 16;
    const int w   = tid >> 5;       // warp 0..7 -> col block w*16
    const int l   = tid & 31;
    const int cg  = l & 3;          // col subgroup of 4
    const int rg  = l >> 2;         // row pair 0..7
    const int cbase = w * 16 + cg * 4;   // first of 4 owned cols (of 128)
    const int r0 = rg * 2;               // owned rows r0, r0+1

    for (int i = tid; i < CAT_ * 128; i += 256) {
        int k = i >> 7;
        int c = i & 127;
        int g = c >> 5;
        Bs[k * BS_STRIDE + c] = g_Wstep[k * SN_ + g * E_ + j0 + (c & 31)];
    }

    float bias_c[4];
#pragma unroll
    for (int q = 0; q < 4; q++) {
        int c = cbase + q;
        int g = c >> 5;
        bias_c[q] = g_bstep[g * E_ + j0 + (c & 31)];
    }
    __syncthreads();

    float* hin = Ha;
    float* hout = Hb;

    for (int t = 0; t < T_; t++) {
        for (int i = tid; i < 16 * 256; i += 256) {
            int row = i >> 8, k = i & 255;
            As[k * AS_STRIDE + row] = __ldcg(&hin[(b0 + row) * E_ + k]);
        }
        {
            int row = tid >> 4, k2 = tid & 15;
            float v = 0.f;
            if (t > 0)
                v = aenc[((size_t)(b0 + row) * T_ + (t - 1)) * A_ + k2];
            As[(E_ + k2) * AS_STRIDE + row] = v;
        }
        __syncthreads();

        float acc0[4] = {0.f, 0.f, 0.f, 0.f};
        float acc1[4] = {0.f, 0.f, 0.f, 0.f};
#pragma unroll 4
        for (int k = 0; k < CAT_; k++) {
            float a0 = As[k * AS_STRIDE + r0];
            float a1 = As[k * AS_STRIDE + r0 + 1];
            float4 b4 = *reinterpret_cast<const float4*>(&Bs[k * BS_STRIDE + cbase]);
            acc0[0] += a0 * b4.x; acc0[1] += a0 * b4.y;
            acc0[2] += a0 * b4.z; acc0[3] += a0 * b4.w;
            acc1[0] += a1 * b4.x; acc1[1] += a1 * b4.y;
            acc1[2] += a1 * b4.z; acc1[3] += a1 * b4.w;
        }

#pragma unroll
        for (int q = 0; q < 4; q++) {
            Ys[r0 * BS_STRIDE + cbase + q]       = acc0[q] + bias_c[q];
            Ys[(r0 + 1) * BS_STRIDE + cbase + q] = acc1[q] + bias_c[q];
        }
        __syncthreads();

        float* o = (t == T_ - 1) ? out : hout;
#pragma unroll
        for (int q = 0; q < 2; q++) {
            int oidx = tid * 2 + q;
            int rr = oidx >> 5;
            int jl = oidx & 31;
            int b = b0 + rr;
            int j = j0 + jl;
            float henc = Ys[rr * BS_STRIDE + jl];
            float ghr  = Ys[rr * BS_STRIDE + 32 + jl];
            float ghz  = Ys[rr * BS_STRIDE + 64 + jl];
            float ghn  = Ys[rr * BS_STRIDE + 96 + jl];
            size_t gb = ((size_t)b * T_ + t) * G3_ + j;
            float ir  = GI[gb];
            float iz  = GI[gb + E_];
            float inn = GI[gb + 2 * E_];
            float r = 1.f / (1.f + expf(-(ir + ghr)));
            float z = 1.f / (1.f + expf(-(iz + ghz)));
            float nn = tanhf(inn + r * ghn);
            o[b * E_ + j] = (1.f - z) * nn + z * henc;
        }

        __threadfence();
        __syncthreads();
        if (tid == 0) {
            atomicAdd(&g_bar, 1u);
            const unsigned target = (unsigned)NB_CTAS * (unsigned)(t + 1);
            while (*((volatile unsigned*)&g_bar) < target)
                __nanosleep(40);
            __threadfence();
        }
        __syncthreads();

        float* tmp = hin; hin = hout; hout = tmp;
    }
}

// ---------------- host orchestration ---------------------------------------------
extern "C" void kernel_launch(void* const* d_in, const int* in_sizes, int n_in,
                              void* d_out, int out_size)
{
    const float* obs = (const float*)d_in[0];
    const float* act = (const float*)d_in[1];
    const float* W1  = (const float*)d_in[2];
    const float* b1  = (const float*)d_in[3];
    const float* g1  = (const float*)d_in[4];
    const float* be1 = (const float*)d_in[5];
    const float* W2  = (const float*)d_in[6];
    const float* b2  = (const float*)d_in[7];
    const float* g2  = (const float*)d_in[8];
    const float* be2 = (const float*)d_in[9];
    const float* W3  = (const float*)d_in[10];
    const float* b3  = (const float*)d_in[11];
    const float* Wih = (const float*)d_in[12];
    const float* bih = (const float*)d_in[13];
    const float* Whh = (const float*)d_in[14];
    const float* bhh = (const float*)d_in[15];
    const float* Whe = (const float*)d_in[16];
    const float* bhe = (const float*)d_in[17];
    const float* Wae = (const float*)d_in[18];
    const float* bae = (const float*)d_in[19];
    float* out = (float*)d_out;

    float *X1p, *X2p, *GIp, *AEp, *W34p, *b34p, *Wstepp, *Hap, *Hbp;
    cudaGetSymbolAddress((void**)&X1p,   g_X1);
    cudaGetSymbolAddress((void**)&X2p,   g_X2);
    cudaGetSymbolAddress((void**)&GIp,   g_GI);
    cudaGetSymbolAddress((void**)&AEp,   g_AENC);
    cudaGetSymbolAddress((void**)&W34p,  g_W34);
    cudaGetSymbolAddress((void**)&b34p,  g_b34v);
    cudaGetSymbolAddress((void**)&Wstepp,g_Wstep);
    cudaGetSymbolAddress((void**)&Hap,   g_Ha);
    cudaGetSymbolAddress((void**)&Hbp,   g_Hb);

    // opt-in smem sizes (idempotent)
    cudaFuncSetAttribute(phaseB_kernel,
                         cudaFuncAttributeMaxDynamicSharedMemorySize, SMEM_B_BYTES);
    cudaFuncSetAttribute(tf32gemm,
                         cudaFuncAttributeMaxDynamicSharedMemorySize, TF_SMEM_BYTES);

    // ---- prep + phase A, ordered so launch #4 = the big obs@W1 tf32gemm ----
    prep_bias_kernel<<<3, 256>>>(b3, bih, Wih, bhe, bhh, Whh);         // 1
    prep_whe_copy<<<(CAT_ * E_ + 255) / 256, 256>>>(Whe);              // 2
    zero_kernel<<<(B_ * E_ + 255) / 256, 256>>>(Hap, B_ * E_);         // 3
    // X1 = obs @ W1 + b1  (independent of preps)
    tf32gemm<<<dim3(H1_ / 128, BT_ / 128), 256, TF_SMEM_BYTES>>>(      // 4
        obs, W1, b1, X1p, BT_, H1_, NIN_, NIN_, H1_, H1_);
    // W34 = W3 @ Wih   [512,768], K=256
    sgemm128<<<dim3(G3_ / 128, (H1_ + 127) / 128), 256>>>(             // 5
        W3, Wih, nullptr, W34p, H1_, G3_, E_, E_, G3_, G3_);
    // Wstep[:, 256:1024] = Whe @ Whh
    sgemm128<<<dim3(G3_ / 128, (CAT_ + 127) / 128), 256>>>(            // 6
        Whe, Whh, nullptr, Wstepp + E_, CAT_, G3_, E_, E_, G3_, SN_);
    bn_elu_kernel<<<dim3(T_, H1_ / 128), 128>>>(X1p, g1, be1);         // 7
    tf32gemm<<<dim3(H1_ / 128, BT_ / 128), 256, TF_SMEM_BYTES>>>(      // 8
        X1p, W2, b2, X2p, BT_, H1_, H1_, H1_, H1_, H1_);
    bn_elu_kernel<<<dim3(T_, H1_ / 128), 128>>>(X2p, g2, be2);         // 9
    tf32gemm<<<dim3(G3_ / 128, BT_ / 128), 256, TF_SMEM_BYTES>>>(      // 10
        X2p, W34p, b34p, GIp, BT_, G3_, H1_, H1_, G3_, G3_);
    aenc_kernel<<<(BT_ * A_ + 255) / 256, 256>>>(act, Wae, bae);       // 11

    // ---- phase B: one persistent kernel, 128 steps, grid barrier per step ----
    phaseB_kernel<<<dim3(8, 16), 256, SMEM_B_BYTES>>>(Hap, Hbp, AEp, GIp, out);
}